// round 10
// baseline (speedup 1.0000x reference)
#include <cuda_runtime.h>
#include <cstdint>

// ---------------------------------------------------------------------------
// C3 layer: x(128,6,256,256) -> out(128,16,252,252), 5x5 VALID convs.
// Direct conv: 4 horizontal px x all 16 oc per thread, scalar fp32 FFMA.
// NEW vs R5: the CTA's input tile (6ch x 8 rows x 256 cols, 48KB) is staged
// into smem with coalesced float4 loads, so the unrolled FFMA loop reads
// ONLY smem (29-cyc LDS, hidden at 4 warps/SMSP) instead of issuing 60
// long-latency LDG.128/thread that capped issue at ~70%.
// ---------------------------------------------------------------------------

__device__ constexpr int POC[6][10] = {
    {0, 4, 5, 6,  9, 10, 11, 12, 14, 15},
    {0, 1, 5, 6,  7, 10, 11, 12, 13, 15},
    {0, 1, 2, 6,  7,  8, 11, 13, 14, 15},
    {1, 2, 3, 6,  7,  8,  9, 12, 14, 15},
    {2, 3, 4, 7,  8,  9, 10, 12, 13, 15},
    {3, 4, 5, 8,  9, 10, 11, 13, 14, 15}
};
__device__ constexpr int POFF[6][10] = {
    {  0, 300, 375, 450, 750,  850,  950, 1050, 1250, 1350},
    { 25,  75, 400, 475, 550,  875,  975, 1075, 1150, 1375},
    { 50, 100, 150, 500, 575,  650, 1000, 1175, 1275, 1400},
    {125, 175, 225, 525, 600,  675,  775, 1100, 1300, 1425},
    {200, 250, 325, 625, 700,  800,  900, 1125, 1200, 1450},
    {275, 350, 425, 725, 825,  925, 1025, 1225, 1325, 1475}
};

__global__ __launch_bounds__(256, 2)
void c3_kernel(const float* __restrict__ x,
               const float* __restrict__ w3, const float* __restrict__ b3,
               const float* __restrict__ w4, const float* __restrict__ b4,
               const float* __restrict__ w6, const float* __restrict__ b6,
               float* __restrict__ out)
{
    // Input tile: 6 channels x 8 rows x 256 cols.
    __shared__ __align__(16) float xs[6][8][256];
    // Weight rows [c][j][ky][0..4], padded to 8 floats (32B).
    __shared__ __align__(16) float wsm[6 * 10 * 5 * 8];
    __shared__ float bsm[16];

    const int tid  = threadIdx.y * 64 + threadIdx.x;
    const int b    = blockIdx.z;
    const int row0 = blockIdx.y * 4;   // first output row of this CTA

    // --- Stage weights ---
    for (int idx = tid; idx < 1500; idx += 256) {
        int kx = idx % 5;
        int t  = idx / 5;
        int ky = t % 5;  t /= 5;
        int j  = t % 10;
        int c  = t / 10;
        int off = POFF[c][j] + ky * 5 + kx;
        float w = (off < 450) ? w3[off]
                : (off < 1350) ? w4[off - 450]
                               : w6[off - 1350];
        wsm[(((c * 10 + j) * 5 + ky) * 8) + kx] = w;
    }
    if (tid < 16) {
        bsm[tid] = (tid < 6) ? b3[tid] : (tid < 15) ? b4[tid - 6] : b6[0];
    }

    // --- Stage input tile: rows row0..row0+7, all 256 cols, 6 channels ---
    // 6*8*256 floats = 3072 float4 loads, 12 per thread, fully coalesced.
    {
        const float4* xv = (const float4*)(x + (size_t)b * 6 * 256 * 256);
        float4* xsv = (float4*)&xs[0][0][0];
        #pragma unroll
        for (int k = 0; k < 12; ++k) {
            int i = tid + k * 256;          // 0..3071
            int c = i >> 9;                 // / 512 (512 float4 per channel)
            int r = (i >> 6) & 7;           // / 64 % 8
            int v = i & 63;                 // float4 within row
            xsv[i] = xv[((size_t)c * 256 + (row0 + r)) * 64 + v];
        }
    }
    __syncthreads();

    const int p  = row0 + threadIdx.y;             // output row
    const int q0 = threadIdx.x * 4;                // 0..252
    const int ql = (q0 > 248) ? 248 : q0;          // tx=63 duplicates tx=62

    float acc[16][4];
    #pragma unroll
    for (int oc = 0; oc < 16; ++oc) {
        float bv = bsm[oc];
        acc[oc][0] = bv; acc[oc][1] = bv; acc[oc][2] = bv; acc[oc][3] = bv;
    }

    #pragma unroll
    for (int c = 0; c < 6; ++c) {
        #pragma unroll
        for (int ky = 0; ky < 5; ++ky) {
            const float* xr = &xs[c][threadIdx.y + ky][ql];
            float4 a0 = *(const float4*)(xr);
            float4 a1 = *(const float4*)(xr + 4);
            float v[8] = {a0.x, a0.y, a0.z, a0.w, a1.x, a1.y, a1.z, a1.w};

            #pragma unroll
            for (int j = 0; j < 10; ++j) {
                const int oc   = POC[c][j];
                const int base = ((c * 10 + j) * 5 + ky) * 8;
                float4 wv = *(const float4*)&wsm[base];
                float  w4v = wsm[base + 4];

                #pragma unroll
                for (int px = 0; px < 4; ++px) {
                    float s = acc[oc][px];
                    s = wv.x * v[px]     + s;
                    s = wv.y * v[px + 1] + s;
                    s = wv.z * v[px + 2] + s;
                    s = wv.w * v[px + 3] + s;
                    s = w4v  * v[px + 4] + s;
                    acc[oc][px] = s;
                }
            }
        }
    }

    if (q0 < 252) {
        #pragma unroll
        for (int oc = 0; oc < 16; ++oc) {
            float4 r;
            r.x = acc[oc][0]; r.y = acc[oc][1];
            r.z = acc[oc][2]; r.w = acc[oc][3];
            *(float4*)(out + (((size_t)b * 16 + oc) * 252 + p) * 252 + q0) = r;
        }
    }
}

extern "C" void kernel_launch(void* const* d_in, const int* in_sizes, int n_in,
                              void* d_out, int out_size)
{
    const float* x  = (const float*)d_in[0];
    const float* w3 = (const float*)d_in[1];
    const float* b3 = (const float*)d_in[2];
    const float* w4 = (const float*)d_in[3];
    const float* b4 = (const float*)d_in[4];
    const float* w6 = (const float*)d_in[5];
    const float* b6 = (const float*)d_in[6];
    float* out = (float*)d_out;

    dim3 block(64, 4, 1);
    dim3 grid(1, 63, 128);      // 63*4 = 252 rows, 128 batch
    c3_kernel<<<grid, block>>>(x, w3, b3, w4, b4, w6, b6, out);
}

// round 11
// speedup vs baseline: 1.4844x; 1.4844x over previous
#include <cuda_runtime.h>
#include <cstdint>

// ---------------------------------------------------------------------------
// C3 layer: x(128,6,256,256) -> out(128,16,252,252), 5x5 VALID convs.
// Direct conv: 4 horizontal px x all 16 oc per thread, scalar fp32 FFMA.
// vs R5: per input channel, ALL 10 LDG.128 (5 rows x 2) are issued
// back-to-back into a register file array BEFORE the FFMA block, raising
// load MLP from ~2 to 10 so the 250-600cyc global latency is covered by
// the 1000-FFMA per-channel body even at 4 warps/SMSP.
// Weights in smem, rows padded to 8 floats; 2 CTAs/SM (126-reg budget).
// ---------------------------------------------------------------------------

__device__ constexpr int POC[6][10] = {
    {0, 4, 5, 6,  9, 10, 11, 12, 14, 15},
    {0, 1, 5, 6,  7, 10, 11, 12, 13, 15},
    {0, 1, 2, 6,  7,  8, 11, 13, 14, 15},
    {1, 2, 3, 6,  7,  8,  9, 12, 14, 15},
    {2, 3, 4, 7,  8,  9, 10, 12, 13, 15},
    {3, 4, 5, 8,  9, 10, 11, 13, 14, 15}
};
__device__ constexpr int POFF[6][10] = {
    {  0, 300, 375, 450, 750,  850,  950, 1050, 1250, 1350},
    { 25,  75, 400, 475, 550,  875,  975, 1075, 1150, 1375},
    { 50, 100, 150, 500, 575,  650, 1000, 1175, 1275, 1400},
    {125, 175, 225, 525, 600,  675,  775, 1100, 1300, 1425},
    {200, 250, 325, 625, 700,  800,  900, 1125, 1200, 1450},
    {275, 350, 425, 725, 825,  925, 1025, 1225, 1325, 1475}
};

__global__ __launch_bounds__(256, 2)
void c3_kernel(const float* __restrict__ x,
               const float* __restrict__ w3, const float* __restrict__ b3,
               const float* __restrict__ w4, const float* __restrict__ b4,
               const float* __restrict__ w6, const float* __restrict__ b6,
               float* __restrict__ out)
{
    // Weight rows [c][j][ky][0..4], padded to 8 floats (32B).
    __shared__ __align__(16) float wsm[6 * 10 * 5 * 8];
    __shared__ float bsm[16];

    const int tid = threadIdx.y * 64 + threadIdx.x;

    for (int idx = tid; idx < 1500; idx += 256) {
        int kx = idx % 5;
        int t  = idx / 5;
        int ky = t % 5;  t /= 5;
        int j  = t % 10;
        int c  = t / 10;
        int off = POFF[c][j] + ky * 5 + kx;
        float w = (off < 450) ? w3[off]
                : (off < 1350) ? w4[off - 450]
                               : w6[off - 1350];
        wsm[(((c * 10 + j) * 5 + ky) * 8) + kx] = w;
    }
    if (tid < 16) {
        bsm[tid] = (tid < 6) ? b3[tid] : (tid < 15) ? b4[tid - 6] : b6[0];
    }
    __syncthreads();

    const int b  = blockIdx.z;
    const int p  = blockIdx.y * 4 + threadIdx.y;   // output row, 0..251
    const int q0 = threadIdx.x * 4;                // output col base
    const int ql = (q0 > 248) ? 248 : q0;          // tx=63 duplicates tx=62

    // 16 oc x 4 px accumulators.
    float acc[16][4];
    #pragma unroll
    for (int oc = 0; oc < 16; ++oc) {
        float bv = bsm[oc];
        acc[oc][0] = bv; acc[oc][1] = bv; acc[oc][2] = bv; acc[oc][3] = bv;
    }

    #pragma unroll
    for (int c = 0; c < 6; ++c) {
        const float* xp = x + (((size_t)b * 6 + c) * 256 + p) * 256 + ql;

        // --- Issue ALL 10 LDG.128 for this channel back-to-back (MLP=10) ---
        float4 a0[5], a1[5];
        #pragma unroll
        for (int ky = 0; ky < 5; ++ky) {
            a0[ky] = *(const float4*)(xp + ky * 256);
            a1[ky] = *(const float4*)(xp + ky * 256 + 4);
        }

        // --- 1000 FFMA body consuming the prefetched rows ---
        #pragma unroll
        for (int ky = 0; ky < 5; ++ky) {
            float v[8] = {a0[ky].x, a0[ky].y, a0[ky].z, a0[ky].w,
                          a1[ky].x, a1[ky].y, a1[ky].z, a1[ky].w};

            #pragma unroll
            for (int j = 0; j < 10; ++j) {
                const int oc   = POC[c][j];
                const int base = ((c * 10 + j) * 5 + ky) * 8;
                float4 wv = *(const float4*)&wsm[base];
                float  w4v = wsm[base + 4];

                #pragma unroll
                for (int px = 0; px < 4; ++px) {
                    float s = acc[oc][px];
                    s = wv.x * v[px]     + s;
                    s = wv.y * v[px + 1] + s;
                    s = wv.z * v[px + 2] + s;
                    s = wv.w * v[px + 3] + s;
                    s = w4v  * v[px + 4] + s;
                    acc[oc][px] = s;
                }
            }
        }
    }

    if (q0 < 252) {
        #pragma unroll
        for (int oc = 0; oc < 16; ++oc) {
            float4 r;
            r.x = acc[oc][0]; r.y = acc[oc][1];
            r.z = acc[oc][2]; r.w = acc[oc][3];
            *(float4*)(out + (((size_t)b * 16 + oc) * 252 + p) * 252 + q0) = r;
        }
    }
}

extern "C" void kernel_launch(void* const* d_in, const int* in_sizes, int n_in,
                              void* d_out, int out_size)
{
    const float* x  = (const float*)d_in[0];
    const float* w3 = (const float*)d_in[1];
    const float* b3 = (const float*)d_in[2];
    const float* w4 = (const float*)d_in[3];
    const float* b4 = (const float*)d_in[4];
    const float* w6 = (const float*)d_in[5];
    const float* b6 = (const float*)d_in[6];
    float* out = (float*)d_out;

    dim3 block(64, 4, 1);
    dim3 grid(1, 63, 128);      // 63*4 = 252 rows, 128 batch
    c3_kernel<<<grid, block>>>(x, w3, b3, w4, b4, w6, b6, out);
}